// round 3
// baseline (speedup 1.0000x reference)
#include <cuda_runtime.h>

#define BATCH   4
#define SEQ     2048
#define DIN     1024
#define NH      16
#define DE      64

// Scratch for projected Q/K/V in [b, h, s, e] layout (32 MB each).
__device__ float g_q[BATCH * NH * SEQ * DE];
__device__ float g_k[BATCH * NH * SEQ * DE];
__device__ float g_v[BATCH * NH * SEQ * DE];

// ============================================================================
// QKV projection:  C[m, h*64+e] = sum_d X[m, d] * W[h, d, e]
// m = b*SEQ + s runs over 8192 rows. One CTA = 128 rows x 1 head (64 cols).
// BK = 16, 256 threads, 8x4 register micro-tile per thread.
// gridDim.z selects {Wq, Wk, Wv} -> {g_q, g_k, g_v}.
// smem: 128*20*4 + 16*64*4 = 14 KB (static, well under 48 KB).
// ============================================================================
__global__ __launch_bounds__(256) void proj_kernel(
    const float* __restrict__ X,
    const float* __restrict__ Wq,
    const float* __restrict__ Wk,
    const float* __restrict__ Wv)
{
    const int h  = blockIdx.x;
    const int m0 = blockIdx.y * 128;
    const float* __restrict__ W   = (blockIdx.z == 0) ? Wq : (blockIdx.z == 1) ? Wk : Wv;
    float*       __restrict__ out = (blockIdx.z == 0) ? g_q : (blockIdx.z == 1) ? g_k : g_v;

    __shared__ __align__(16) float As[128][20];   // [m][k], pad 16->20 floats
    __shared__ __align__(16) float Bs[16][64];    // [k][e]

    const int tid = threadIdx.x;
    const int tx = tid & 15;          // col group: cols tx*4 .. tx*4+3
    const int ty = tid >> 4;          // row group: rows ty*8 .. ty*8+7

    const int ar  = tid >> 2;         // A load row (0..63, and +64)
    const int akg = (tid & 3) << 2;   // A load k offset {0,4,8,12}
    const int bd  = tid >> 4;         // B load row 0..15
    const int be  = (tid & 15) << 2;  // B load col offset

    const float* __restrict__ Wh = W + (size_t)h * DIN * DE;

    float acc[8][4];
#pragma unroll
    for (int i = 0; i < 8; i++)
#pragma unroll
        for (int j = 0; j < 4; j++) acc[i][j] = 0.f;

    for (int k0 = 0; k0 < DIN; k0 += 16) {
        float4 a0 = *(const float4*)(X + (size_t)(m0 + ar)      * DIN + k0 + akg);
        float4 a1 = *(const float4*)(X + (size_t)(m0 + ar + 64) * DIN + k0 + akg);
        float4 b0 = *(const float4*)(Wh + (size_t)(k0 + bd) * DE + be);
        __syncthreads();   // previous iteration's compute done before overwrite
        *(float4*)(&As[ar][akg])      = a0;
        *(float4*)(&As[ar + 64][akg]) = a1;
        *(float4*)(&Bs[bd][be])       = b0;
        __syncthreads();
#pragma unroll
        for (int k = 0; k < 16; k++) {
            float a[8];
#pragma unroll
            for (int i = 0; i < 8; i++) a[i] = As[ty * 8 + i][k];
            float4 bb = *(const float4*)(&Bs[k][tx * 4]);
#pragma unroll
            for (int i = 0; i < 8; i++) {
                acc[i][0] += a[i] * bb.x;
                acc[i][1] += a[i] * bb.y;
                acc[i][2] += a[i] * bb.z;
                acc[i][3] += a[i] * bb.w;
            }
        }
    }

#pragma unroll
    for (int i = 0; i < 8; i++) {
        const int m = m0 + ty * 8 + i;
        const int b = m / SEQ;
        const int s = m % SEQ;
        float4 v = make_float4(acc[i][0], acc[i][1], acc[i][2], acc[i][3]);
        *(float4*)(out + ((size_t)((b * NH + h) * SEQ + s)) * DE + tx * 4) = v;
    }
}

// ============================================================================
// Causal flash attention (fp32, online softmax, chunked).
// One CTA = one (b, h, 128-row q tile). 128 threads, 1 query row per thread.
// Per thread: q row (64 regs, pre-scaled by 1/8) + O accumulator (64 regs).
// K/V 64x64 key tiles staged in smem (32 KB static total — no score buffer).
// Scores are processed in 16-key register chunks with per-chunk online-
// softmax update (conditional rescale — rarely taken after early tiles).
// q-tile order reversed so heaviest CTAs (most key tiles) launch first.
// ============================================================================
__global__ __launch_bounds__(128) void attn_kernel(float* __restrict__ out)
{
    const int qt = (gridDim.x - 1) - blockIdx.x;
    const int h  = blockIdx.y;
    const int b  = blockIdx.z;
    const int t  = threadIdx.x;

    const float* __restrict__ Q = g_q + (size_t)((b * NH + h) * SEQ) * DE;
    const float* __restrict__ K = g_k + (size_t)((b * NH + h) * SEQ) * DE;
    const float* __restrict__ V = g_v + (size_t)((b * NH + h) * SEQ) * DE;

    __shared__ __align__(16) float Ks[64][64];   // 16 KB
    __shared__ __align__(16) float Vs[64][64];   // 16 KB

    const int qrow = qt * 128 + t;

    float q[64];
#pragma unroll
    for (int e4 = 0; e4 < 16; e4++) {
        float4 v = *(const float4*)(Q + (size_t)qrow * DE + e4 * 4);
        q[e4 * 4 + 0] = v.x * 0.125f;   // fold 1/sqrt(64) into q
        q[e4 * 4 + 1] = v.y * 0.125f;
        q[e4 * 4 + 2] = v.z * 0.125f;
        q[e4 * 4 + 3] = v.w * 0.125f;
    }

    float O[64];
#pragma unroll
    for (int e = 0; e < 64; e++) O[e] = 0.f;
    float mrun = -1e30f, lrun = 0.f;

    const int lrow = t >> 4;          // 0..7
    const int lcol = (t & 15) * 4;    // 0..60

    const int nkt = 2 * qt + 2;       // key tiles covering rows 0 .. qt*128+127
    for (int kt = 0; kt < nkt; kt++) {
        __syncthreads();   // previous tile fully consumed before overwrite
#pragma unroll
        for (int r = 0; r < 8; r++) {
            const int row = r * 8 + lrow;
            *(float4*)(&Ks[row][lcol]) = *(const float4*)(K + (size_t)(kt * 64 + row) * DE + lcol);
            *(float4*)(&Vs[row][lcol]) = *(const float4*)(V + (size_t)(kt * 64 + row) * DE + lcol);
        }
        __syncthreads();

        // 4 chunks of 16 keys; scores live in registers.
#pragma unroll
        for (int c = 0; c < 4; c++) {
            const int jbase = kt * 64 + c * 16;
            float s[16];
            float mc = -1e30f;
#pragma unroll
            for (int j = 0; j < 16; j++) {
                const int jj = c * 16 + j;
                float acc = 0.f;
#pragma unroll
                for (int e4 = 0; e4 < 16; e4++) {
                    float4 kv = *(const float4*)(&Ks[jj][e4 * 4]);
                    acc += q[e4 * 4 + 0] * kv.x + q[e4 * 4 + 1] * kv.y
                         + q[e4 * 4 + 2] * kv.z + q[e4 * 4 + 3] * kv.w;
                }
                s[j] = (jbase + j > qrow) ? -1e30f : acc;   // causal mask
                mc = fmaxf(mc, s[j]);
            }

            const float mnew = fmaxf(mrun, mc);
            if (mnew > mrun) {           // rescale only when max advances
                const float corr = __expf(mrun - mnew);
                lrun *= corr;
#pragma unroll
                for (int e = 0; e < 64; e++) O[e] *= corr;
                mrun = mnew;
            }

#pragma unroll
            for (int j = 0; j < 16; j++) {
                const int jj = c * 16 + j;
                const float p = __expf(s[j] - mrun);   // masked -> 0
                lrun += p;
#pragma unroll
                for (int e4 = 0; e4 < 16; e4++) {
                    float4 vv = *(const float4*)(&Vs[jj][e4 * 4]);
                    O[e4 * 4 + 0] += p * vv.x;
                    O[e4 * 4 + 1] += p * vv.y;
                    O[e4 * 4 + 2] += p * vv.z;
                    O[e4 * 4 + 3] += p * vv.w;
                }
            }
        }
    }

    const float inv = 1.f / lrun;
    float* __restrict__ o = out + ((size_t)(b * SEQ + qrow) * (NH * DE)) + h * DE;
#pragma unroll
    for (int e4 = 0; e4 < 16; e4++) {
        float4 v = make_float4(O[e4 * 4 + 0] * inv, O[e4 * 4 + 1] * inv,
                               O[e4 * 4 + 2] * inv, O[e4 * 4 + 3] * inv);
        *(float4*)(o + e4 * 4) = v;
    }
}

// ============================================================================
extern "C" void kernel_launch(void* const* d_in, const int* in_sizes, int n_in,
                              void* d_out, int out_size) {
    (void)in_sizes; (void)n_in; (void)out_size;
    const float* X  = (const float*)d_in[0];
    const float* Wq = (const float*)d_in[1];
    const float* Wk = (const float*)d_in[2];
    const float* Wv = (const float*)d_in[3];
    float* out = (float*)d_out;

    dim3 gp(NH, (BATCH * SEQ) / 128, 3);
    proj_kernel<<<gp, 256>>>(X, Wq, Wk, Wv);

    dim3 ga(SEQ / 128, NH, BATCH);
    attn_kernel<<<ga, 128>>>(out);
}

// round 6
// speedup vs baseline: 1.0257x; 1.0257x over previous
#include <cuda_runtime.h>

#define BATCH   4
#define SEQ     2048
#define DIN     1024
#define NH      16
#define DE      64

// Scratch for projected Q/K/V in [b, h, s, e] layout (32 MB each).
__device__ float g_q[BATCH * NH * SEQ * DE];
__device__ float g_k[BATCH * NH * SEQ * DE];
__device__ float g_v[BATCH * NH * SEQ * DE];

// ============================================================================
// QKV projection:  C[m, h*64+e] = sum_d X[m, d] * W[h, d, e]
// One CTA = 128 rows x 1 head (64 cols). BK = 16, 256 threads, 8x4 micro-tile.
// A-tile stored k-major (As[k][m], row stride 132 floats, 16B-aligned) so the
// inner loop fetches 8 A-values with 2 LDS.128 instead of 8 scalar LDS.
// gridDim.z selects {Wq, Wk, Wv} -> {g_q, g_k, g_v}.
// ============================================================================
__global__ __launch_bounds__(256) void proj_kernel(
    const float* __restrict__ X,
    const float* __restrict__ Wq,
    const float* __restrict__ Wk,
    const float* __restrict__ Wv)
{
    const int h  = blockIdx.x;
    const int m0 = blockIdx.y * 128;
    const float* __restrict__ W   = (blockIdx.z == 0) ? Wq : (blockIdx.z == 1) ? Wk : Wv;
    float*       __restrict__ out = (blockIdx.z == 0) ? g_q : (blockIdx.z == 1) ? g_k : g_v;

    __shared__ __align__(16) float As[16][132];   // [k][m], 132*4B row = 16B-aligned
    __shared__ __align__(16) float Bs[16][64];    // [k][e]

    const int tid = threadIdx.x;
    const int tx = tid & 15;          // col group: cols tx*4 .. tx*4+3
    const int ty = tid >> 4;          // row group: rows ty*8 .. ty*8+7

    const int ar  = tid >> 2;         // A load row (0..63, and +64)
    const int akg = (tid & 3) << 2;   // A load k offset {0,4,8,12}
    const int bd  = tid >> 4;         // B load row 0..15
    const int be  = (tid & 15) << 2;  // B load col offset

    const float* __restrict__ Wh = W + (size_t)h * DIN * DE;

    float acc[8][4];
#pragma unroll
    for (int i = 0; i < 8; i++)
#pragma unroll
        for (int j = 0; j < 4; j++) acc[i][j] = 0.f;

    for (int k0 = 0; k0 < DIN; k0 += 16) {
        float4 a0 = *(const float4*)(X + (size_t)(m0 + ar)      * DIN + k0 + akg);
        float4 a1 = *(const float4*)(X + (size_t)(m0 + ar + 64) * DIN + k0 + akg);
        float4 b0 = *(const float4*)(Wh + (size_t)(k0 + bd) * DE + be);
        __syncthreads();   // previous iteration's compute done before overwrite
        As[akg + 0][ar] = a0.x;  As[akg + 1][ar] = a0.y;
        As[akg + 2][ar] = a0.z;  As[akg + 3][ar] = a0.w;
        As[akg + 0][ar + 64] = a1.x;  As[akg + 1][ar + 64] = a1.y;
        As[akg + 2][ar + 64] = a1.z;  As[akg + 3][ar + 64] = a1.w;
        *(float4*)(&Bs[bd][be]) = b0;
        __syncthreads();
#pragma unroll
        for (int k = 0; k < 16; k++) {
            float4 aa0 = *(const float4*)(&As[k][ty * 8]);
            float4 aa1 = *(const float4*)(&As[k][ty * 8 + 4]);
            float4 bb  = *(const float4*)(&Bs[k][tx * 4]);
            const float a[8] = { aa0.x, aa0.y, aa0.z, aa0.w,
                                 aa1.x, aa1.y, aa1.z, aa1.w };
#pragma unroll
            for (int i = 0; i < 8; i++) {
                acc[i][0] += a[i] * bb.x;
                acc[i][1] += a[i] * bb.y;
                acc[i][2] += a[i] * bb.z;
                acc[i][3] += a[i] * bb.w;
            }
        }
    }

#pragma unroll
    for (int i = 0; i < 8; i++) {
        const int m = m0 + ty * 8 + i;
        const int b = m / SEQ;
        const int s = m % SEQ;
        float4 v = make_float4(acc[i][0], acc[i][1], acc[i][2], acc[i][3]);
        *(float4*)(out + ((size_t)((b * NH + h) * SEQ + s)) * DE + tx * 4) = v;
    }
}

// ============================================================================
// Causal flash attention (fp32, online softmax, chunked).
// One CTA = one (b, h, 128-row q tile). 128 threads, 1 query row per thread.
// Scores use 4 rotating partial accumulators to break the FFMA RAW chain
// (chain length 64 -> 4, dependent reuse distance 16 FFMAs).
// K/V 64x64 key tiles staged in smem (32 KB static).
// ============================================================================
__global__ __launch_bounds__(128) void attn_kernel(float* __restrict__ out)
{
    const int qt = (gridDim.x - 1) - blockIdx.x;
    const int h  = blockIdx.y;
    const int b  = blockIdx.z;
    const int t  = threadIdx.x;

    const float* __restrict__ Q = g_q + (size_t)((b * NH + h) * SEQ) * DE;
    const float* __restrict__ K = g_k + (size_t)((b * NH + h) * SEQ) * DE;
    const float* __restrict__ V = g_v + (size_t)((b * NH + h) * SEQ) * DE;

    __shared__ __align__(16) float Ks[64][64];   // 16 KB
    __shared__ __align__(16) float Vs[64][64];   // 16 KB

    const int qrow = qt * 128 + t;

    float q[64];
#pragma unroll
    for (int e4 = 0; e4 < 16; e4++) {
        float4 v = *(const float4*)(Q + (size_t)qrow * DE + e4 * 4);
        q[e4 * 4 + 0] = v.x * 0.125f;   // fold 1/sqrt(64) into q
        q[e4 * 4 + 1] = v.y * 0.125f;
        q[e4 * 4 + 2] = v.z * 0.125f;
        q[e4 * 4 + 3] = v.w * 0.125f;
    }

    float O[64];
#pragma unroll
    for (int e = 0; e < 64; e++) O[e] = 0.f;
    float mrun = -1e30f, lrun = 0.f;

    const int lrow = t >> 4;          // 0..7
    const int lcol = (t & 15) * 4;    // 0..60

    const int nkt = 2 * qt + 2;       // key tiles covering rows 0 .. qt*128+127
    for (int kt = 0; kt < nkt; kt++) {
        __syncthreads();   // previous tile fully consumed before overwrite
#pragma unroll
        for (int r = 0; r < 8; r++) {
            const int row = r * 8 + lrow;
            *(float4*)(&Ks[row][lcol]) = *(const float4*)(K + (size_t)(kt * 64 + row) * DE + lcol);
            *(float4*)(&Vs[row][lcol]) = *(const float4*)(V + (size_t)(kt * 64 + row) * DE + lcol);
        }
        __syncthreads();

        // 4 chunks of 16 keys; scores live in registers.
#pragma unroll
        for (int c = 0; c < 4; c++) {
            const int jbase = kt * 64 + c * 16;
            float s[16];
            float mc = -1e30f;
#pragma unroll
            for (int j = 0; j < 16; j++) {
                const int jj = c * 16 + j;
                // 4 rotating partial accumulators -> 4 independent FFMA chains
                float p0 = 0.f, p1 = 0.f, p2 = 0.f, p3 = 0.f;
#pragma unroll
                for (int e4 = 0; e4 < 16; e4 += 4) {
                    float4 k0 = *(const float4*)(&Ks[jj][(e4 + 0) * 4]);
                    float4 k1 = *(const float4*)(&Ks[jj][(e4 + 1) * 4]);
                    float4 k2 = *(const float4*)(&Ks[jj][(e4 + 2) * 4]);
                    float4 k3 = *(const float4*)(&Ks[jj][(e4 + 3) * 4]);
                    p0 += q[(e4+0)*4+0]*k0.x + q[(e4+0)*4+1]*k0.y + q[(e4+0)*4+2]*k0.z + q[(e4+0)*4+3]*k0.w;
                    p1 += q[(e4+1)*4+0]*k1.x + q[(e4+1)*4+1]*k1.y + q[(e4+1)*4+2]*k1.z + q[(e4+1)*4+3]*k1.w;
                    p2 += q[(e4+2)*4+0]*k2.x + q[(e4+2)*4+1]*k2.y + q[(e4+2)*4+2]*k2.z + q[(e4+2)*4+3]*k2.w;
                    p3 += q[(e4+3)*4+0]*k3.x + q[(e4+3)*4+1]*k3.y + q[(e4+3)*4+2]*k3.z + q[(e4+3)*4+3]*k3.w;
                }
                const float acc = (p0 + p1) + (p2 + p3);
                s[j] = (jbase + j > qrow) ? -1e30f : acc;   // causal mask
                mc = fmaxf(mc, s[j]);
            }

            const float mnew = fmaxf(mrun, mc);
            if (mnew > mrun) {           // rescale only when max advances
                const float corr = __expf(mrun - mnew);
                lrun *= corr;
#pragma unroll
                for (int e = 0; e < 64; e++) O[e] *= corr;
                mrun = mnew;
            }

#pragma unroll
            for (int j = 0; j < 16; j++) {
                const int jj = c * 16 + j;
                const float p = __expf(s[j] - mrun);   // masked -> 0
                lrun += p;
#pragma unroll
                for (int e4 = 0; e4 < 16; e4++) {
                    float4 vv = *(const float4*)(&Vs[jj][e4 * 4]);
                    O[e4 * 4 + 0] += p * vv.x;
                    O[e4 * 4 + 1] += p * vv.y;
                    O[e4 * 4 + 2] += p * vv.z;
                    O[e4 * 4 + 3] += p * vv.w;
                }
            }
        }
    }

    const float inv = 1.f / lrun;
    float* __restrict__ o = out + ((size_t)(b * SEQ + qrow) * (NH * DE)) + h * DE;
#pragma unroll
    for (int e4 = 0; e4 < 16; e4++) {
        float4 v = make_float4(O[e4 * 4 + 0] * inv, O[e4 * 4 + 1] * inv,
                               O[e4 * 4 + 2] * inv, O[e4 * 4 + 3] * inv);
        *(float4*)(o + e4 * 4) = v;
    }
}

// ============================================================================
extern "C" void kernel_launch(void* const* d_in, const int* in_sizes, int n_in,
                              void* d_out, int out_size) {
    (void)in_sizes; (void)n_in; (void)out_size;
    const float* X  = (const float*)d_in[0];
    const float* Wq = (const float*)d_in[1];
    const float* Wk = (const float*)d_in[2];
    const float* Wv = (const float*)d_in[3];
    float* out = (float*)d_out;

    dim3 gp(NH, (BATCH * SEQ) / 128, 3);
    proj_kernel<<<gp, 256>>>(X, Wq, Wk, Wv);

    dim3 ga(SEQ / 128, NH, BATCH);
    attn_kernel<<<ga, 128>>>(out);
}

// round 8
// speedup vs baseline: 1.5868x; 1.5470x over previous
#include <cuda_runtime.h>

#define BATCH   4
#define SEQ     2048
#define DIN     1024
#define NH      16
#define DE      64

// Scratch for projected Q/K/V in [b, h, s, e] layout (32 MB each).
__device__ float g_q[BATCH * NH * SEQ * DE];
__device__ float g_k[BATCH * NH * SEQ * DE];
__device__ float g_v[BATCH * NH * SEQ * DE];

// ============================================================================
// QKV projection:  C[m, h*64+e] = sum_d X[m, d] * W[h, d, e]
// One CTA = 128 rows x 1 head (64 cols). BK = 16, 256 threads, 8x4 micro-tile.
// A-tile stored k-major (As[k][m]) so the inner loop fetches 8 A-values with
// 2 LDS.128. (Unchanged from R6 — this version measured faster.)
// ============================================================================
__global__ __launch_bounds__(256) void proj_kernel(
    const float* __restrict__ X,
    const float* __restrict__ Wq,
    const float* __restrict__ Wk,
    const float* __restrict__ Wv)
{
    const int h  = blockIdx.x;
    const int m0 = blockIdx.y * 128;
    const float* __restrict__ W   = (blockIdx.z == 0) ? Wq : (blockIdx.z == 1) ? Wk : Wv;
    float*       __restrict__ out = (blockIdx.z == 0) ? g_q : (blockIdx.z == 1) ? g_k : g_v;

    __shared__ __align__(16) float As[16][132];   // [k][m], 132*4B row = 16B-aligned
    __shared__ __align__(16) float Bs[16][64];    // [k][e]

    const int tid = threadIdx.x;
    const int tx = tid & 15;
    const int ty = tid >> 4;

    const int ar  = tid >> 2;
    const int akg = (tid & 3) << 2;
    const int bd  = tid >> 4;
    const int be  = (tid & 15) << 2;

    const float* __restrict__ Wh = W + (size_t)h * DIN * DE;

    float acc[8][4];
#pragma unroll
    for (int i = 0; i < 8; i++)
#pragma unroll
        for (int j = 0; j < 4; j++) acc[i][j] = 0.f;

    for (int k0 = 0; k0 < DIN; k0 += 16) {
        float4 a0 = *(const float4*)(X + (size_t)(m0 + ar)      * DIN + k0 + akg);
        float4 a1 = *(const float4*)(X + (size_t)(m0 + ar + 64) * DIN + k0 + akg);
        float4 b0 = *(const float4*)(Wh + (size_t)(k0 + bd) * DE + be);
        __syncthreads();
        As[akg + 0][ar] = a0.x;  As[akg + 1][ar] = a0.y;
        As[akg + 2][ar] = a0.z;  As[akg + 3][ar] = a0.w;
        As[akg + 0][ar + 64] = a1.x;  As[akg + 1][ar + 64] = a1.y;
        As[akg + 2][ar + 64] = a1.z;  As[akg + 3][ar + 64] = a1.w;
        *(float4*)(&Bs[bd][be]) = b0;
        __syncthreads();
#pragma unroll
        for (int k = 0; k < 16; k++) {
            float4 aa0 = *(const float4*)(&As[k][ty * 8]);
            float4 aa1 = *(const float4*)(&As[k][ty * 8 + 4]);
            float4 bb  = *(const float4*)(&Bs[k][tx * 4]);
            const float a[8] = { aa0.x, aa0.y, aa0.z, aa0.w,
                                 aa1.x, aa1.y, aa1.z, aa1.w };
#pragma unroll
            for (int i = 0; i < 8; i++) {
                acc[i][0] += a[i] * bb.x;
                acc[i][1] += a[i] * bb.y;
                acc[i][2] += a[i] * bb.z;
                acc[i][3] += a[i] * bb.w;
            }
        }
    }

#pragma unroll
    for (int i = 0; i < 8; i++) {
        const int m = m0 + ty * 8 + i;
        const int b = m / SEQ;
        const int s = m % SEQ;
        float4 v = make_float4(acc[i][0], acc[i][1], acc[i][2], acc[i][3]);
        *(float4*)(out + ((size_t)((b * NH + h) * SEQ + s)) * DE + tx * 4) = v;
    }
}

// ============================================================================
// Causal flash attention (fp32, online softmax, pair-split head dim).
// One CTA = one (b, h, 128-row q tile), 256 threads. Lane pair (2i, 2i+1)
// shares q-row i of the warp's 16 rows; each lane owns the 8 float4-groups of
// matching parity (interleaved halves -> conflict-free smem: even/odd lanes
// broadcast two addresses 16B apart, disjoint banks). Score = 32-dim partial
// dot + shfl_xor(.,1); softmax state is bit-identical across the pair.
// Halved register state (q[32]+O[32]) -> 2 CTAs/SM = 16 warps (was 8).
// ============================================================================
__global__ __launch_bounds__(256, 2) void attn_kernel(float* __restrict__ out)
{
    const int qt = (gridDim.x - 1) - blockIdx.x;
    const int h  = blockIdx.y;
    const int b  = blockIdx.z;
    const int t  = threadIdx.x;

    const int row  = ((t >> 5) << 4) + ((t & 31) >> 1);  // warp*16 + lane/2
    const int half = t & 1;                              // group parity owned

    const float* __restrict__ Q = g_q + (size_t)((b * NH + h) * SEQ) * DE;
    const float* __restrict__ K = g_k + (size_t)((b * NH + h) * SEQ) * DE;
    const float* __restrict__ V = g_v + (size_t)((b * NH + h) * SEQ) * DE;

    __shared__ __align__(16) float Ks[64][64];   // 16 KB
    __shared__ __align__(16) float Vs[64][64];   // 16 KB

    const int qrow = qt * 128 + row;

    // q regs: 8 float4-groups of parity `half` (dims (2*g4+half)*4 ..+3)
    float q[32];
#pragma unroll
    for (int g4 = 0; g4 < 8; g4++) {
        float4 v = *(const float4*)(Q + (size_t)qrow * DE + (2 * g4 + half) * 4);
        q[g4 * 4 + 0] = v.x * 0.125f;   // fold 1/sqrt(64) into q
        q[g4 * 4 + 1] = v.y * 0.125f;
        q[g4 * 4 + 2] = v.z * 0.125f;
        q[g4 * 4 + 3] = v.w * 0.125f;
    }

    float O[32];
#pragma unroll
    for (int e = 0; e < 32; e++) O[e] = 0.f;
    float mrun = -1e30f, lrun = 0.f;

    const int nkt = 2 * qt + 2;       // key tiles covering rows 0 .. qt*128+127
    for (int kt = 0; kt < nkt; kt++) {
        __syncthreads();   // previous tile fully consumed before overwrite
#pragma unroll
        for (int it = 0; it < 4; it++) {
            const int fi = it * 256 + t;        // 0..1023 = 64 rows x 16 groups
            const int r  = fi >> 4;
            const int g  = (fi & 15) << 2;
            *(float4*)(&Ks[r][g]) = *(const float4*)(K + (size_t)(kt * 64 + r) * DE + g);
            *(float4*)(&Vs[r][g]) = *(const float4*)(V + (size_t)(kt * 64 + r) * DE + g);
        }
        __syncthreads();

        // 4 chunks of 16 keys; scores live in registers.
#pragma unroll
        for (int c = 0; c < 4; c++) {
            const int jbase = kt * 64 + c * 16;
            float s[16];
            float mc = -1e30f;
#pragma unroll
            for (int j = 0; j < 16; j++) {
                const int jj = c * 16 + j;
                float p0 = 0.f, p1 = 0.f;
#pragma unroll
                for (int g4 = 0; g4 < 8; g4 += 2) {
                    float4 ka = *(const float4*)(&Ks[jj][(2 * g4 + half) * 4]);
                    float4 kb = *(const float4*)(&Ks[jj][(2 * (g4 + 1) + half) * 4]);
                    p0 += q[g4*4+0]*ka.x + q[g4*4+1]*ka.y + q[g4*4+2]*ka.z + q[g4*4+3]*ka.w;
                    p1 += q[(g4+1)*4+0]*kb.x + q[(g4+1)*4+1]*kb.y + q[(g4+1)*4+2]*kb.z + q[(g4+1)*4+3]*kb.w;
                }
                float part = p0 + p1;
                part += __shfl_xor_sync(0xffffffffu, part, 1);   // combine halves
                s[j] = (jbase + j > qrow) ? -1e30f : part;       // causal mask
                mc = fmaxf(mc, s[j]);
            }

            const float mnew = fmaxf(mrun, mc);
            if (mnew > mrun) {           // rescale only when max advances
                const float corr = __expf(mrun - mnew);
                lrun *= corr;
#pragma unroll
                for (int e = 0; e < 32; e++) O[e] *= corr;
                mrun = mnew;
            }

#pragma unroll
            for (int j = 0; j < 16; j++) {
                const int jj = c * 16 + j;
                const float p = __expf(s[j] - mrun);   // masked -> 0
                lrun += p;
#pragma unroll
                for (int g4 = 0; g4 < 8; g4++) {
                    float4 vv = *(const float4*)(&Vs[jj][(2 * g4 + half) * 4]);
                    O[g4 * 4 + 0] += p * vv.x;
                    O[g4 * 4 + 1] += p * vv.y;
                    O[g4 * 4 + 2] += p * vv.z;
                    O[g4 * 4 + 3] += p * vv.w;
                }
            }
        }
    }

    const float inv = 1.f / lrun;
    float* __restrict__ o = out + ((size_t)(b * SEQ + qrow) * (NH * DE)) + h * DE;
#pragma unroll
    for (int g4 = 0; g4 < 8; g4++) {
        float4 v = make_float4(O[g4 * 4 + 0] * inv, O[g4 * 4 + 1] * inv,
                               O[g4 * 4 + 2] * inv, O[g4 * 4 + 3] * inv);
        *(float4*)(o + (2 * g4 + half) * 4) = v;
    }
}

// ============================================================================
extern "C" void kernel_launch(void* const* d_in, const int* in_sizes, int n_in,
                              void* d_out, int out_size) {
    (void)in_sizes; (void)n_in; (void)out_size;
    const float* X  = (const float*)d_in[0];
    const float* Wq = (const float*)d_in[1];
    const float* Wk = (const float*)d_in[2];
    const float* Wv = (const float*)d_in[3];
    float* out = (float*)d_out;

    dim3 gp(NH, (BATCH * SEQ) / 128, 3);
    proj_kernel<<<gp, 256>>>(X, Wq, Wk, Wv);

    dim3 ga(SEQ / 128, NH, BATCH);
    attn_kernel<<<ga, 256>>>(out);
}

// round 10
// speedup vs baseline: 1.9578x; 1.2338x over previous
#include <cuda_runtime.h>
#include <cuda_bf16.h>
#include <cstdint>

#define BATCH   4
#define SEQ     2048
#define DIN     1024
#define NH      16
#define DE      64
#define MROWS   (BATCH * SEQ)   // 8192

// ---------------------------------------------------------------------------
// Device scratch (static — no allocation).
// ---------------------------------------------------------------------------
__device__ float g_q[BATCH * NH * SEQ * DE];
__device__ float g_k[BATCH * NH * SEQ * DE];
__device__ float g_v[BATCH * NH * SEQ * DE];

__device__ __align__(16) __nv_bfloat16 g_xhi[MROWS * DIN];
__device__ __align__(16) __nv_bfloat16 g_xlo[MROWS * DIN];
// W transposed+split: [z][h][e][k], k contiguous (1024)
__device__ __align__(16) __nv_bfloat16 g_wthi[3 * NH * DE * DIN];
__device__ __align__(16) __nv_bfloat16 g_wtlo[3 * NH * DE * DIN];

// ---------------------------------------------------------------------------
// Warp-level MMA helpers (baseline PTX — works on sm_100 non-'a' target).
// ---------------------------------------------------------------------------
__device__ __forceinline__ uint32_t smem_to_u32(const void* p) {
    uint32_t a;
    asm("{ .reg .u64 t; cvta.to.shared.u64 t, %1; cvt.u32.u64 %0, t; }" : "=r"(a) : "l"(p));
    return a;
}
__device__ __forceinline__ void ldsm_x4(uint32_t* r, uint32_t addr) {
    asm volatile("ldmatrix.sync.aligned.m8n8.x4.shared.b16 {%0,%1,%2,%3}, [%4];"
                 : "=r"(r[0]), "=r"(r[1]), "=r"(r[2]), "=r"(r[3]) : "r"(addr));
}
__device__ __forceinline__ void mma_bf16(float* c, const uint32_t* a, const uint32_t* b) {
    asm volatile("mma.sync.aligned.m16n8k16.row.col.f32.bf16.bf16.f32 "
                 "{%0,%1,%2,%3}, {%4,%5,%6,%7}, {%8,%9}, {%0,%1,%2,%3};"
                 : "+f"(c[0]), "+f"(c[1]), "+f"(c[2]), "+f"(c[3])
                 : "r"(a[0]), "r"(a[1]), "r"(a[2]), "r"(a[3]), "r"(b[0]), "r"(b[1]));
}
#define SMEM_SWIZZLE_128B(o) ((o) ^ (((o) >> 3) & 0x70))

// ---------------------------------------------------------------------------
// Convert X -> bf16 hi/lo (same [m][k] layout).
// ---------------------------------------------------------------------------
__global__ __launch_bounds__(256) void convert_x_kernel(const float* __restrict__ X) {
    const int i = blockIdx.x * 256 + threadIdx.x;   // float4 index
    float4 v = ((const float4*)X)[i];
    float xs[4] = {v.x, v.y, v.z, v.w};
    union { __nv_bfloat16 h[4]; uint2 u; } hi, lo;
#pragma unroll
    for (int j = 0; j < 4; j++) {
        __nv_bfloat16 h = __float2bfloat16(xs[j]);
        hi.h[j] = h;
        lo.h[j] = __float2bfloat16(xs[j] - __bfloat162float(h));
    }
    ((uint2*)g_xhi)[i] = hi.u;
    ((uint2*)g_xlo)[i] = lo.u;
}

// ---------------------------------------------------------------------------
// Convert + transpose W: [z][h][k][e] fp32 -> [z][h][e][k] bf16 hi/lo.
// ---------------------------------------------------------------------------
__global__ __launch_bounds__(256) void convert_w_kernel(
    const float* __restrict__ Wq, const float* __restrict__ Wk, const float* __restrict__ Wv) {
    const int zh = blockIdx.x;
    const int z = zh / NH, h = zh % NH;
    const float* __restrict__ W = (z == 0) ? Wq : (z == 1) ? Wk : Wv;
    const float* __restrict__ Wh = W + (size_t)h * DIN * DE;
    __nv_bfloat16* __restrict__ oh = g_wthi + (size_t)zh * DE * DIN;
    __nv_bfloat16* __restrict__ ol = g_wtlo + (size_t)zh * DE * DIN;
    for (int j = threadIdx.x; j < DE * DIN; j += 256) {
        const int e = j / DIN, k = j % DIN;
        const float x = Wh[(size_t)k * DE + e];
        const __nv_bfloat16 hb = __float2bfloat16(x);
        oh[j] = hb;
        ol[j] = __float2bfloat16(x - __bfloat162float(hb));
    }
}

// ---------------------------------------------------------------------------
// mma.sync QKV projection (bf16 hi/lo split, 3 terms, fp32 accum).
// CTA = 128 m-rows x 2 heads (128 n). 8 warps: 4m x 2n; warp tile 32m x 64n
// (one head). K staged in 16 chunks of 64, SW128-swizzled 128B rows; A/B
// fragments via ldmatrix.x4 with canonical m16n8k16 addressing.
// Dynamic smem 64KB: Xhi | Xlo | Whi(2 heads) | Wlo.
// ---------------------------------------------------------------------------
#define SM_XHI 0
#define SM_XLO 16384
#define SM_WHI 32768
#define SM_WLO 49152
#define PROJ_SMEM 65536

__global__ __launch_bounds__(256) void proj_mma_kernel() {
    extern __shared__ __align__(1024) char smem[];
    const uint32_t sb = smem_to_u32(smem);
    const int tid = threadIdx.x, w = tid >> 5, lane = tid & 31;
    const int wm = w & 3, wn = w >> 1 >> 1;      // wm 0..3, wn 0..1
    const int mt = blockIdx.x;                   // 0..63
    const int z  = blockIdx.y;                   // 0..2
    const int hg = blockIdx.z;                   // 0..7 (2 heads each)
    const int m0 = mt * 128;
    float* __restrict__ out = (z == 0) ? g_q : (z == 1) ? g_k : g_v;

    float acc[2][8][4];
#pragma unroll
    for (int mi = 0; mi < 2; mi++)
#pragma unroll
        for (int ni = 0; ni < 8; ni++)
#pragma unroll
            for (int r = 0; r < 4; r++) acc[mi][ni][r] = 0.f;

    // ldmatrix per-lane address components (pre-swizzle, within tile)
    const int a_row = wm * 32 + (lane & 15);     // + mi*16
    const int a_kb  = (lane >> 4) * 16;          // k-half byte offset
    const int b_row = (lane & 7) + ((lane >> 4) << 3);   // n within 16-block
    const int b_kb  = ((lane >> 3) & 1) * 16;

    for (int c = 0; c < 16; c++) {
        const int k0 = c * 64;
        __syncthreads();   // previous chunk's MMAs consumed smem
        // X tiles: 128 rows x 64 bf16 (128B rows, SW128), hi + lo
        for (int i = tid; i < 1024; i += 256) {
            const int r = i >> 3, g = i & 7;
            const uint32_t off = SMEM_SWIZZLE_128B((uint32_t)(r * 128 + g * 16));
            const size_t src = (size_t)(m0 + r) * DIN + k0 + g * 8;
            *(uint4*)(smem + SM_XHI + off) = *(const uint4*)(g_xhi + src);
            *(uint4*)(smem + SM_XLO + off) = *(const uint4*)(g_xlo + src);
        }
        // W tiles: 2 heads x (64 n-rows x 64 k), hi + lo
        for (int i = tid; i < 1024; i += 256) {
            const int hidx = i >> 9;
            const int j = i & 511, r = j >> 3, g = j & 7;
            const size_t src = ((size_t)((z * NH + hg * 2 + hidx) * DE + r)) * DIN + k0 + g * 8;
            const uint32_t off = hidx * 8192 + SMEM_SWIZZLE_128B((uint32_t)(r * 128 + g * 16));
            *(uint4*)(smem + SM_WHI + off) = *(const uint4*)(g_wthi + src);
            *(uint4*)(smem + SM_WLO + off) = *(const uint4*)(g_wtlo + src);
        }
        __syncthreads();

#pragma unroll 1
        for (int ks = 0; ks < 4; ks++) {
            const int kso = ks * 32;             // k16 = 32 bytes
            uint32_t ahi[2][4], alo[2][4];
#pragma unroll
            for (int mi = 0; mi < 2; mi++) {
                const uint32_t off =
                    SMEM_SWIZZLE_128B((uint32_t)((a_row + mi * 16) * 128 + a_kb + kso));
                ldsm_x4(ahi[mi], sb + SM_XHI + off);
                ldsm_x4(alo[mi], sb + SM_XLO + off);
            }
            uint32_t bhi[8][2], blo[8][2];
#pragma unroll
            for (int nb = 0; nb < 4; nb++) {
                const uint32_t off = wn * 8192 +
                    SMEM_SWIZZLE_128B((uint32_t)((nb * 16 + b_row) * 128 + b_kb + kso));
                uint32_t t4[4];
                ldsm_x4(t4, sb + SM_WHI + off);
                bhi[2 * nb][0] = t4[0]; bhi[2 * nb][1] = t4[1];
                bhi[2 * nb + 1][0] = t4[2]; bhi[2 * nb + 1][1] = t4[3];
                ldsm_x4(t4, sb + SM_WLO + off);
                blo[2 * nb][0] = t4[0]; blo[2 * nb][1] = t4[1];
                blo[2 * nb + 1][0] = t4[2]; blo[2 * nb + 1][1] = t4[3];
            }
#pragma unroll
            for (int mi = 0; mi < 2; mi++)
#pragma unroll
                for (int ni = 0; ni < 8; ni++) {
                    mma_bf16(acc[mi][ni], ahi[mi], bhi[ni]);   // xh*wh
                    mma_bf16(acc[mi][ni], ahi[mi], blo[ni]);   // xh*wl
                    mma_bf16(acc[mi][ni], alo[mi], bhi[ni]);   // xl*wh
                }
        }
    }

    // Epilogue: D fragment (m16n8): c0,c1 at (row=lane/4, col=2*(lane%4)),
    // c2,c3 at (row+8, col). Write float2 pairs.
    const int h = hg * 2 + wn;
#pragma unroll
    for (int mi = 0; mi < 2; mi++) {
#pragma unroll
        for (int ni = 0; ni < 8; ni++) {
            const int e = ni * 8 + (lane & 3) * 2;
#pragma unroll
            for (int half = 0; half < 2; half++) {
                const int m = m0 + wm * 32 + mi * 16 + (lane >> 2) + half * 8;
                const int b = m / SEQ, s = m % SEQ;
                float* __restrict__ o =
                    out + ((size_t)((b * NH + h) * SEQ + s)) * DE + e;
                *(float2*)o = make_float2(acc[mi][ni][half * 2], acc[mi][ni][half * 2 + 1]);
            }
        }
    }
}

// ---------------------------------------------------------------------------
// Causal flash attention — unchanged R8 winner (pair-split, 16 warps/SM).
// ---------------------------------------------------------------------------
__global__ __launch_bounds__(256, 2) void attn_kernel(float* __restrict__ out)
{
    const int qt = (gridDim.x - 1) - blockIdx.x;
    const int h  = blockIdx.y;
    const int b  = blockIdx.z;
    const int t  = threadIdx.x;

    const int row  = ((t >> 5) << 4) + ((t & 31) >> 1);
    const int half = t & 1;

    const float* __restrict__ Q = g_q + (size_t)((b * NH + h) * SEQ) * DE;
    const float* __restrict__ K = g_k + (size_t)((b * NH + h) * SEQ) * DE;
    const float* __restrict__ V = g_v + (size_t)((b * NH + h) * SEQ) * DE;

    __shared__ __align__(16) float Ks[64][64];
    __shared__ __align__(16) float Vs[64][64];

    const int qrow = qt * 128 + row;

    float q[32];
#pragma unroll
    for (int g4 = 0; g4 < 8; g4++) {
        float4 v = *(const float4*)(Q + (size_t)qrow * DE + (2 * g4 + half) * 4);
        q[g4 * 4 + 0] = v.x * 0.125f;
        q[g4 * 4 + 1] = v.y * 0.125f;
        q[g4 * 4 + 2] = v.z * 0.125f;
        q[g4 * 4 + 3] = v.w * 0.125f;
    }

    float O[32];
#pragma unroll
    for (int e = 0; e < 32; e++) O[e] = 0.f;
    float mrun = -1e30f, lrun = 0.f;

    const int nkt = 2 * qt + 2;
    for (int kt = 0; kt < nkt; kt++) {
        __syncthreads();
#pragma unroll
        for (int it = 0; it < 4; it++) {
            const int fi = it * 256 + t;
            const int r  = fi >> 4;
            const int g  = (fi & 15) << 2;
            *(float4*)(&Ks[r][g]) = *(const float4*)(K + (size_t)(kt * 64 + r) * DE + g);
            *(float4*)(&Vs[r][g]) = *(const float4*)(V + (size_t)(kt * 64 + r) * DE + g);
        }
        __syncthreads();

#pragma unroll
        for (int c = 0; c < 4; c++) {
            const int jbase = kt * 64 + c * 16;
            float s[16];
            float mc = -1e30f;
#pragma unroll
            for (int j = 0; j < 16; j++) {
                const int jj = c * 16 + j;
                float p0 = 0.f, p1 = 0.f;
#pragma unroll
                for (int g4 = 0; g4 < 8; g4 += 2) {
                    float4 ka = *(const float4*)(&Ks[jj][(2 * g4 + half) * 4]);
                    float4 kb = *(const float4*)(&Ks[jj][(2 * (g4 + 1) + half) * 4]);
                    p0 += q[g4*4+0]*ka.x + q[g4*4+1]*ka.y + q[g4*4+2]*ka.z + q[g4*4+3]*ka.w;
                    p1 += q[(g4+1)*4+0]*kb.x + q[(g4+1)*4+1]*kb.y + q[(g4+1)*4+2]*kb.z + q[(g4+1)*4+3]*kb.w;
                }
                float part = p0 + p1;
                part += __shfl_xor_sync(0xffffffffu, part, 1);
                s[j] = (jbase + j > qrow) ? -1e30f : part;
                mc = fmaxf(mc, s[j]);
            }

            const float mnew = fmaxf(mrun, mc);
            if (mnew > mrun) {
                const float corr = __expf(mrun - mnew);
                lrun *= corr;
#pragma unroll
                for (int e = 0; e < 32; e++) O[e] *= corr;
                mrun = mnew;
            }

#pragma unroll
            for (int j = 0; j < 16; j++) {
                const int jj = c * 16 + j;
                const float p = __expf(s[j] - mrun);
                lrun += p;
#pragma unroll
                for (int g4 = 0; g4 < 8; g4++) {
                    float4 vv = *(const float4*)(&Vs[jj][(2 * g4 + half) * 4]);
                    O[g4 * 4 + 0] += p * vv.x;
                    O[g4 * 4 + 1] += p * vv.y;
                    O[g4 * 4 + 2] += p * vv.z;
                    O[g4 * 4 + 3] += p * vv.w;
                }
            }
        }
    }

    const float inv = 1.f / lrun;
    float* __restrict__ o = out + ((size_t)(b * SEQ + qrow) * (NH * DE)) + h * DE;
#pragma unroll
    for (int g4 = 0; g4 < 8; g4++) {
        float4 v = make_float4(O[g4 * 4 + 0] * inv, O[g4 * 4 + 1] * inv,
                               O[g4 * 4 + 2] * inv, O[g4 * 4 + 3] * inv);
        *(float4*)(o + (2 * g4 + half) * 4) = v;
    }
}

// ---------------------------------------------------------------------------
extern "C" void kernel_launch(void* const* d_in, const int* in_sizes, int n_in,
                              void* d_out, int out_size) {
    (void)in_sizes; (void)n_in; (void)out_size;
    const float* X  = (const float*)d_in[0];
    const float* Wq = (const float*)d_in[1];
    const float* Wk = (const float*)d_in[2];
    const float* Wv = (const float*)d_in[3];
    float* out = (float*)d_out;

    cudaFuncSetAttribute(proj_mma_kernel,
                         cudaFuncAttributeMaxDynamicSharedMemorySize, PROJ_SMEM);

    convert_x_kernel<<<(MROWS * DIN / 4) / 256, 256>>>(X);
    convert_w_kernel<<<3 * NH, 256>>>(Wq, Wk, Wv);

    dim3 gp(64, 3, 8);
    proj_mma_kernel<<<gp, 256, PROJ_SMEM>>>();

    dim3 ga(SEQ / 128, NH, BATCH);
    attn_kernel<<<ga, 256>>>(out);
}